// round 7
// baseline (speedup 1.0000x reference)
#include <cuda_runtime.h>
#include <cuda_fp16.h>

// NCA step via tensor cores, fp16 m16n8k16 (f32 accumulate), transposed
// coalesced epilogue. kappa-permuted hidden dim chains L1 D-frags into L2
// A-frags in registers. B=32, C=16, H=W=256, HID=128.

#define NB   32
#define NC   16
#define NH   256
#define NW   256
#define HID  128
#define HW   (NH * NW)

#define TLX  16
#define TLY  16
#define NPIX (TLX * TLY)
#define HSX  (TLX + 2)
#define HSY  (TLY + 2)
#define YSTW 28            // Y row stride (u32 words)
#define DXST 260           // dx smem stride per channel (words): pad for banks

__device__ float    g_ch3[NB * HW];
__device__ unsigned g_w1p[16 * 3 * 64];   // 3072 f16x2 words
__device__ unsigned g_w2p[8 * 2 * 64];    // 1024 f16x2 words

// smem layout (4B words)
#define SM_W1  0                          // 3072
#define SM_W2  (SM_W1 + 3072)             // 1024
#define SM_B1  (SM_W2 + 1024)             // 128
#define SM_UR  (SM_B1 + 128)              // 256
#define SM_XS  (SM_UR + 256)              // 5184
#define SM_YS  (SM_XS + HSY * HSX * NC)   // max(256*28, 16*260)=7168
#define SM_DX  SM_YS                      // overlays Y after MMA reads
#define SM_WORDS (SM_YS + NPIX * YSTW)
#define SM_BYTES (SM_WORDS * 4)

__device__ __forceinline__ unsigned pk16(float lo, float hi) {
    __half2 h = __floats2half2_rn(lo, hi);
    return *(unsigned*)&h;
}
__device__ __forceinline__ unsigned relu2(unsigned v) {
    __half2 z = __float2half2_rn(0.f);
    __half2 r = __hmax2(*(__half2*)&v, z);
    return *(unsigned*)&r;
}

__device__ __forceinline__ void mma16(float c[4], const unsigned a[4],
                                      unsigned b0, unsigned b1) {
    asm volatile(
        "mma.sync.aligned.m16n8k16.row.col.f32.f16.f16.f32 "
        "{%0,%1,%2,%3}, {%4,%5,%6,%7}, {%8,%9}, {%0,%1,%2,%3};"
        : "+f"(c[0]), "+f"(c[1]), "+f"(c[2]), "+f"(c[3])
        : "r"(a[0]), "r"(a[1]), "r"(a[2]), "r"(a[3]), "r"(b0), "r"(b1));
}

__device__ __forceinline__ int kappa(int s) { return (s >> 1) + 4 * (s & 1); }

__global__ void nca_prep(const float* __restrict__ w1, const float* __restrict__ w2) {
    int i = blockIdx.x * 256 + threadIdx.x;
    if (i < 3072) {
        int r = i & 1, lane = (i >> 1) & 31;
        int kg2 = (i >> 6) % 3, g = i / 192;
        int t4 = lane & 3, q = lane >> 2;
        int h  = 8 * g + kappa(q);
        int f0 = 16 * kg2 + 2 * t4 + 8 * r;
        g_w1p[i] = pk16(w1[h * 48 + f0], w1[h * 48 + f0 + 1]);
    }
    int j = i - 3072;
    if (j >= 0 && j < 1024) {
        int r = j & 1, lane = (j >> 1) & 31;
        int ng = (j >> 6) & 1, p = j >> 7;
        int t4 = lane & 3, q = lane >> 2;
        int o  = q + 8 * ng;
        int h0 = 16 * p + 8 * r + t4;
        g_w2p[j] = pk16(w2[o * HID + h0], w2[o * HID + h0 + 4]);
    }
}

extern __shared__ float smem[];

__global__ __launch_bounds__(256, 3)
void nca_main(const float* __restrict__ x, const float* __restrict__ ur,
              const float* __restrict__ b1, float* __restrict__ out) {
    const int b   = blockIdx.z;
    const int ty0 = blockIdx.y * TLY;
    const int tx0 = blockIdx.x * TLX;
    const int tid = threadIdx.x;

    unsigned* w1s = (unsigned*)(smem + SM_W1);
    unsigned* w2s = (unsigned*)(smem + SM_W2);
    float*    b1s = smem + SM_B1;
    float*    urs = smem + SM_UR;
    float*    xs  = smem + SM_XS;
    unsigned* ysw = (unsigned*)(smem + SM_YS);
    float*    dxs = smem + SM_DX;

    // ---- stage packed weights ----
    {
        const uint4* s1 = (const uint4*)g_w1p;
        uint4*       d1 = (uint4*)w1s;
        #pragma unroll
        for (int i = tid; i < 3072 / 4; i += 256) d1[i] = s1[i];
        const uint4* s2 = (const uint4*)g_w2p;
        uint4*       d2p = (uint4*)w2s;
        if (tid < 1024 / 4) d2p[tid] = s2[tid];
        if (tid < HID) b1s[tid] = b1[tid];
    }

    // ---- stage halo tile + update gate (pre-converted to 0/1) ----
    {
        const float* xb = x + (size_t)b * NC * HW;
        for (int i = tid; i < NC * HSY * HSX; i += 256) {
            int c = i / (HSY * HSX);
            int rem = i - c * (HSY * HSX);
            int yy = rem / HSX, xx = rem - (rem / HSX) * HSX;
            int gy = ty0 + yy - 1, gx = tx0 + xx - 1;
            float v = 0.f;
            if (gy >= 0 && gy < NH && gx >= 0 && gx < NW)
                v = xb[c * HW + gy * NW + gx];
            xs[i] = v;
        }
        int py = tid / TLX, px = tid % TLX;
        urs[tid] = (ur[(size_t)b * HW + (ty0 + py) * NW + (tx0 + px)] <= 0.5f)
                   ? 1.f : 0.f;
    }
    __syncthreads();

    // ---- perception -> f16x2 Y rows ----
    {
        int py = tid / TLX, px = tid % TLX;
        unsigned* yr = ysw + tid * YSTW;
        float pend = 0.f;
        #pragma unroll
        for (int c = 0; c < NC; ++c) {
            const float* p = xs + c * (HSY * HSX) + py * HSX + px;
            float a00 = p[0],        a01 = p[1],           a02 = p[2];
            float a10 = p[HSX],      a11 = p[HSX + 1],     a12 = p[HSX + 2];
            float a20 = p[2 * HSX],  a21 = p[2 * HSX + 1], a22 = p[2 * HSX + 2];
            float sx = (a02 - a00 + 2.f * (a12 - a10) + a22 - a20) * 0.125f;
            float sy = (a20 - a00 + 2.f * (a21 - a01) + a22 - a02) * 0.125f;
            if ((c & 1) == 0) {
                yr[(3 * c) / 2] = pk16(a11, sx);
                pend = sy;
            } else {
                yr[(3 * c - 1) / 2] = pk16(pend, a11);
                yr[(3 * c + 1) / 2] = pk16(sx, sy);
            }
        }
    }
    __syncthreads();

    // ---- MLP on tensor cores ----
    const int w    = tid >> 5;
    const int lane = tid & 31;
    const int qid  = lane >> 2;
    const int r4   = lane & 3;

    unsigned ya[2][3][4];
    #pragma unroll
    for (int t = 0; t < 2; ++t) {
        int p0 = (2 * w + t) * TLX + qid;
        const unsigned* y0 = ysw + p0 * YSTW;
        const unsigned* y1 = ysw + (p0 + 8) * YSTW;
        #pragma unroll
        for (int kg = 0; kg < 3; ++kg) {
            ya[t][kg][0] = y0[8 * kg + r4];
            ya[t][kg][1] = y1[8 * kg + r4];
            ya[t][kg][2] = y0[8 * kg + r4 + 4];
            ya[t][kg][3] = y1[8 * kg + r4 + 4];
        }
    }

    float d2[2][2][4];
    #pragma unroll
    for (int t = 0; t < 2; ++t)
        #pragma unroll
        for (int n = 0; n < 2; ++n)
            #pragma unroll
            for (int e = 0; e < 4; ++e) d2[t][n][e] = 0.f;

    #pragma unroll 2
    for (int p = 0; p < 8; ++p) {
        float c0[2][4], c1[2][4];
        #pragma unroll
        for (int gg = 0; gg < 2; ++gg) {
            int g = 2 * p + gg;
            float bias0 = b1s[8 * g + r4];
            float bias1 = b1s[8 * g + r4 + 4];
            c0[gg][0] = bias0; c0[gg][1] = bias1; c0[gg][2] = bias0; c0[gg][3] = bias1;
            c1[gg][0] = bias0; c1[gg][1] = bias1; c1[gg][2] = bias0; c1[gg][3] = bias1;
            const uint2* w1g = (const uint2*)w1s + (g * 3) * 32 + lane;
            #pragma unroll
            for (int kg = 0; kg < 3; ++kg) {
                uint2 bb = w1g[kg * 32];
                mma16(c0[gg], ya[0][kg], bb.x, bb.y);
                mma16(c1[gg], ya[1][kg], bb.x, bb.y);
            }
        }
        unsigned h0[4] = { relu2(pk16(c0[0][0], c0[0][1])),
                           relu2(pk16(c0[0][2], c0[0][3])),
                           relu2(pk16(c0[1][0], c0[1][1])),
                           relu2(pk16(c0[1][2], c0[1][3])) };
        unsigned h1[4] = { relu2(pk16(c1[0][0], c1[0][1])),
                           relu2(pk16(c1[0][2], c1[0][3])),
                           relu2(pk16(c1[1][0], c1[1][1])),
                           relu2(pk16(c1[1][2], c1[1][3])) };
        const uint2* w2g = (const uint2*)w2s + (p * 2) * 32 + lane;
        #pragma unroll
        for (int ng = 0; ng < 2; ++ng) {
            uint2 bb = w2g[ng * 32];
            mma16(d2[0][ng], h0, bb.x, bb.y);
            mma16(d2[1][ng], h1, bb.x, bb.y);
        }
    }

    // ---- dx -> smem (padded stride, conflict-free) ----
    __syncthreads();   // all ys reads done; safe to overlay
    #pragma unroll
    for (int t = 0; t < 2; ++t) {
        int py = 2 * w + t;
        #pragma unroll
        for (int ng = 0; ng < 2; ++ng) {
            #pragma unroll
            for (int bq = 0; bq < 2; ++bq) {
                int ch = 8 * ng + 2 * r4 + bq;
                float* dr = dxs + ch * DXST + py * TLX;
                dr[qid]     = d2[t][ng][bq];
                dr[qid + 8] = d2[t][ng][bq + 2];
            }
        }
    }
    __syncthreads();

    // ---- coalesced epilogue: v = x + dx*u, STG.128 ----
    {
        float* ob = out + (size_t)b * NC * HW;
        #pragma unroll
        for (int it = 0; it < 4; ++it) {
            int u    = tid + 256 * it;           // 0..1023
            int quad = u & 3;
            int row  = (u >> 2) & 15;
            int ch   = u >> 6;
            const float4 d  = *(const float4*)(dxs + ch * DXST + row * TLX + quad * 4);
            const float4 uv = *(const float4*)(urs + row * TLX + quad * 4);
            const float* xc = xs + ch * (HSY * HSX) + (row + 1) * HSX + 1 + quad * 4;
            float4 v;
            v.x = fmaf(d.x, uv.x, xc[0]);
            v.y = fmaf(d.y, uv.y, xc[1]);
            v.z = fmaf(d.z, uv.z, xc[2]);
            v.w = fmaf(d.w, uv.w, xc[3]);
            int gy = ty0 + row, gx = tx0 + quad * 4;
            *(float4*)(ob + (size_t)ch * HW + gy * NW + gx) = v;
            if (ch == 3)
                *(float4*)(g_ch3 + (size_t)b * HW + gy * NW + gx) = v;
        }
    }
}

// mask: 4 pixels/thread, shared column maxes
__global__ void nca_mask(const float* __restrict__ x, float* __restrict__ out) {
    int idx = blockIdx.x * blockDim.x + threadIdx.x;
    if (idx >= NB * HW / 4) return;
    int b = idx / (HW / 4);
    int r = idx - b * (HW / 4);
    int i  = r / (NW / 4);
    int j0 = (r - i * (NW / 4)) * 4;

    const float* x3 = x + ((size_t)b * NC + 3) * HW;
    const float* n3 = g_ch3 + (size_t)b * HW;

    float cm0[6], cm1[6];
    #pragma unroll
    for (int k = 0; k < 6; ++k) {
        int jj = j0 - 1 + k;
        float a = -1e30f, c = -1e30f;
        if (jj >= 0 && jj < NW) {
            #pragma unroll
            for (int dy = -1; dy <= 1; ++dy) {
                int yy = i + dy;
                if (yy < 0 || yy >= NH) continue;
                a = fmaxf(a, x3[yy * NW + jj]);
                c = fmaxf(c, n3[yy * NW + jj]);
            }
        }
        cm0[k] = a; cm1[k] = c;
    }
    #pragma unroll
    for (int q = 0; q < 4; ++q) {
        float m0 = fmaxf(fmaxf(cm0[q], cm0[q + 1]), cm0[q + 2]);
        float m1 = fmaxf(fmaxf(cm1[q], cm1[q + 1]), cm1[q + 2]);
        if (!((m0 > 0.1f) && (m1 > 0.1f))) {
            float* ob = out + (size_t)b * NC * HW + i * NW + j0 + q;
            #pragma unroll
            for (int c = 0; c < NC; ++c) ob[(size_t)c * HW] = 0.f;
        }
    }
}

extern "C" void kernel_launch(void* const* d_in, const int* in_sizes, int n_in,
                              void* d_out, int out_size) {
    const float* x  = (const float*)d_in[0];
    const float* ur = (const float*)d_in[1];
    const float* w1 = (const float*)d_in[2];
    const float* b1 = (const float*)d_in[3];
    const float* w2 = (const float*)d_in[4];
    float* out = (float*)d_out;

    cudaFuncSetAttribute(nca_main, cudaFuncAttributeMaxDynamicSharedMemorySize, SM_BYTES);

    nca_prep<<<16, 256>>>(w1, w2);

    dim3 grid(NW / TLX, NH / TLY, NB);
    nca_main<<<grid, 256, SM_BYTES>>>(x, ur, b1, out);

    nca_mask<<<(NB * HW / 4 + 255) / 256, 256>>>(x, out);
}

// round 9
// speedup vs baseline: 1.0855x; 1.0855x over previous
#include <cuda_runtime.h>
#include <cuda_fp16.h>

// NCA step via tensor cores: L1 = m16n8k16 f16*f16+f16 (packed D feeds L2 A
// directly, identity hidden permutation), L2 = m16n8k16 f16*f16+f32.
// Bias enters as packed f16x2 C-init. B=32, C=16, H=W=256, HID=128.

#define NB   32
#define NC   16
#define NH   256
#define NW   256
#define HID  128
#define HW   (NH * NW)

#define TLX  16
#define TLY  16
#define NPIX (TLX * TLY)
#define HSX  (TLX + 2)
#define HSY  (TLY + 2)
#define YSTW 28            // Y row stride in u32 words

__device__ float    g_ch3[NB * HW];
__device__ unsigned g_w1p[16 * 3 * 64];   // 3072 f16x2 words (B-frag layout, L1)
__device__ unsigned g_w2p[8 * 2 * 64];    // 1024 f16x2 words (B-frag layout, L2)
__device__ unsigned g_b1p[64];            // packed bias: [g][t4] = (b[8g+2t4], b[8g+2t4+1])

// smem layout (4B words)
#define SM_W1  0                          // 3072
#define SM_W2  (SM_W1 + 3072)             // 1024
#define SM_B1P (SM_W2 + 1024)             // 64
#define SM_UR  (SM_B1P + 64)              // 256
#define SM_XS  (SM_UR + 256)              // 5184
#define SM_YS  (SM_XS + HSY * HSX * NC)   // 7168
#define SM_WORDS (SM_YS + NPIX * YSTW)
#define SM_BYTES (SM_WORDS * 4)

__device__ __forceinline__ unsigned pk16(float lo, float hi) {
    __half2 h = __floats2half2_rn(lo, hi);
    return *(unsigned*)&h;
}
__device__ __forceinline__ unsigned relu2(unsigned v) {
    __half2 z = __float2half2_rn(0.f);
    __half2 r = __hmax2(*(__half2*)&v, z);
    return *(unsigned*)&r;
}

// L1: f16 accumulate, D packed f16x2 (2 regs)
__device__ __forceinline__ void mma16h(unsigned c[2], const unsigned a[4],
                                       unsigned b0, unsigned b1) {
    asm volatile(
        "mma.sync.aligned.m16n8k16.row.col.f16.f16.f16.f16 "
        "{%0,%1}, {%2,%3,%4,%5}, {%6,%7}, {%0,%1};"
        : "+r"(c[0]), "+r"(c[1])
        : "r"(a[0]), "r"(a[1]), "r"(a[2]), "r"(a[3]), "r"(b0), "r"(b1));
}
// L2: f32 accumulate
__device__ __forceinline__ void mma16f(float c[4], const unsigned a[4],
                                       unsigned b0, unsigned b1) {
    asm volatile(
        "mma.sync.aligned.m16n8k16.row.col.f32.f16.f16.f32 "
        "{%0,%1,%2,%3}, {%4,%5,%6,%7}, {%8,%9}, {%0,%1,%2,%3};"
        : "+f"(c[0]), "+f"(c[1]), "+f"(c[2]), "+f"(c[3])
        : "r"(a[0]), "r"(a[1]), "r"(a[2]), "r"(a[3]), "r"(b0), "r"(b1));
}

// ---- prep: fragment-ready f16x2 weight packing (identity hidden perm) ----
__global__ void nca_prep(const float* __restrict__ w1, const float* __restrict__ b1,
                         const float* __restrict__ w2) {
    int i = blockIdx.x * 256 + threadIdx.x;
    if (i < 3072) {
        // i = ((g*3 + kg2)*32 + lane)*2 + r
        int r = i & 1, lane = (i >> 1) & 31;
        int kg2 = (i >> 6) % 3, g = i / 192;
        int t4 = lane & 3, q = lane >> 2;
        int h  = 8 * g + q;                       // identity (no kappa)
        int f0 = 16 * kg2 + 2 * t4 + 8 * r;
        g_w1p[i] = pk16(w1[h * 48 + f0], w1[h * 48 + f0 + 1]);
    }
    int j = i - 3072;
    if (j >= 0 && j < 1024) {
        // j = ((p*2 + ng)*32 + lane)*2 + r
        int r = j & 1, lane = (j >> 1) & 31;
        int ng = (j >> 6) & 1, p = j >> 7;
        int t4 = lane & 3, q = lane >> 2;
        int o  = q + 8 * ng;
        int h0 = 16 * p + 8 * r + 2 * t4;         // natural pairs
        g_w2p[j] = pk16(w2[o * HID + h0], w2[o * HID + h0 + 1]);
    }
    int k = i - 4096;
    if (k >= 0 && k < 64) {
        int g = k >> 2, t4 = k & 3;
        g_b1p[k] = pk16(b1[8 * g + 2 * t4], b1[8 * g + 2 * t4 + 1]);
    }
}

extern __shared__ float smem[];

__global__ __launch_bounds__(256, 3)
void nca_main(const float* __restrict__ x, const float* __restrict__ ur,
              float* __restrict__ out) {
    const int b   = blockIdx.z;
    const int ty0 = blockIdx.y * TLY;
    const int tx0 = blockIdx.x * TLX;
    const int tid = threadIdx.x;

    unsigned* w1s  = (unsigned*)(smem + SM_W1);
    unsigned* w2s  = (unsigned*)(smem + SM_W2);
    unsigned* b1ps = (unsigned*)(smem + SM_B1P);
    float*    urs  = smem + SM_UR;
    float*    xs   = smem + SM_XS;
    unsigned* ysw  = (unsigned*)(smem + SM_YS);

    // ---- stage packed weights ----
    {
        const uint4* s1 = (const uint4*)g_w1p;
        uint4*       d1 = (uint4*)w1s;
        #pragma unroll
        for (int i = tid; i < 3072 / 4; i += 256) d1[i] = s1[i];
        const uint4* s2 = (const uint4*)g_w2p;
        uint4*       d2p = (uint4*)w2s;
        if (tid < 1024 / 4) d2p[tid] = s2[tid];
        if (tid < 64) b1ps[tid] = g_b1p[tid];
    }

    // ---- stage halo tile + pre-gated update mask ----
    {
        const float* xb = x + (size_t)b * NC * HW;
        for (int i = tid; i < NC * HSY * HSX; i += 256) {
            int c = i / (HSY * HSX);
            int rem = i - c * (HSY * HSX);
            int yy = rem / HSX, xx = rem - (rem / HSX) * HSX;
            int gy = ty0 + yy - 1, gx = tx0 + xx - 1;
            float v = 0.f;
            if (gy >= 0 && gy < NH && gx >= 0 && gx < NW)
                v = xb[c * HW + gy * NW + gx];
            xs[i] = v;
        }
        int py = tid / TLX, px = tid % TLX;
        urs[tid] = (ur[(size_t)b * HW + (ty0 + py) * NW + (tx0 + px)] <= 0.5f)
                   ? 1.f : 0.f;
    }
    __syncthreads();

    // ---- perception -> f16x2 Y rows (48 halves = 24 words) ----
    {
        int py = tid / TLX, px = tid % TLX;
        unsigned* yr = ysw + tid * YSTW;
        float pend = 0.f;
        #pragma unroll
        for (int c = 0; c < NC; ++c) {
            const float* p = xs + c * (HSY * HSX) + py * HSX + px;
            float a00 = p[0],        a01 = p[1],           a02 = p[2];
            float a10 = p[HSX],      a11 = p[HSX + 1],     a12 = p[HSX + 2];
            float a20 = p[2 * HSX],  a21 = p[2 * HSX + 1], a22 = p[2 * HSX + 2];
            float sx = (a02 - a00 + 2.f * (a12 - a10) + a22 - a20) * 0.125f;
            float sy = (a20 - a00 + 2.f * (a21 - a01) + a22 - a02) * 0.125f;
            if ((c & 1) == 0) {
                yr[(3 * c) / 2] = pk16(a11, sx);
                pend = sy;
            } else {
                yr[(3 * c - 1) / 2] = pk16(pend, a11);
                yr[(3 * c + 1) / 2] = pk16(sx, sy);
            }
        }
    }
    __syncthreads();

    // ---- MLP on tensor cores ----
    const int w    = tid >> 5;
    const int lane = tid & 31;
    const int qid  = lane >> 2;
    const int r4   = lane & 3;

    unsigned ya[2][3][4];
    #pragma unroll
    for (int t = 0; t < 2; ++t) {
        int p0 = (2 * w + t) * TLX + qid;
        const unsigned* y0 = ysw + p0 * YSTW;
        const unsigned* y1 = ysw + (p0 + 8) * YSTW;
        #pragma unroll
        for (int kg = 0; kg < 3; ++kg) {
            ya[t][kg][0] = y0[8 * kg + r4];
            ya[t][kg][1] = y1[8 * kg + r4];
            ya[t][kg][2] = y0[8 * kg + r4 + 4];
            ya[t][kg][3] = y1[8 * kg + r4 + 4];
        }
    }

    float d2[2][2][4];
    #pragma unroll
    for (int t = 0; t < 2; ++t)
        #pragma unroll
        for (int n = 0; n < 2; ++n)
            #pragma unroll
            for (int e = 0; e < 4; ++e) d2[t][n][e] = 0.f;

    #pragma unroll
    for (int p = 0; p < 8; ++p) {
        unsigned h0[4], h1[4];
        #pragma unroll
        for (int gg = 0; gg < 2; ++gg) {
            int g = 2 * p + gg;
            unsigned bias = b1ps[4 * g + r4];
            unsigned c0[2] = {bias, bias};
            unsigned c1[2] = {bias, bias};
            const uint2* w1g = (const uint2*)w1s + (g * 3) * 32 + lane;
            #pragma unroll
            for (int kg = 0; kg < 3; ++kg) {
                uint2 bb = w1g[kg * 32];
                mma16h(c0, ya[0][kg], bb.x, bb.y);
                mma16h(c1, ya[1][kg], bb.x, bb.y);
            }
            h0[2 * gg + 0] = relu2(c0[0]);
            h0[2 * gg + 1] = relu2(c0[1]);
            h1[2 * gg + 0] = relu2(c1[0]);
            h1[2 * gg + 1] = relu2(c1[1]);
        }
        const uint2* w2g = (const uint2*)w2s + (p * 2) * 32 + lane;
        #pragma unroll
        for (int ng = 0; ng < 2; ++ng) {
            uint2 bb = w2g[ng * 32];
            mma16f(d2[0][ng], h0, bb.x, bb.y);
            mma16f(d2[1][ng], h1, bb.x, bb.y);
        }
    }

    // ---- epilogue: x + dx*update (exact fp32 x from xs) ----
    #pragma unroll
    for (int t = 0; t < 2; ++t) {
        int py = 2 * w + t;
        int gy = ty0 + py;
        int p0 = py * TLX + qid;
        int p1 = p0 + 8;
        float u0 = urs[p0];
        float u1 = urs[p1];
        int gx0 = tx0 + qid, gx1 = gx0 + 8;
        float* ob = out + (size_t)b * NC * HW + gy * NW;
        #pragma unroll
        for (int ng = 0; ng < 2; ++ng) {
            #pragma unroll
            for (int bq = 0; bq < 2; ++bq) {
                int ch = 8 * ng + 2 * r4 + bq;
                const float* xc = xs + ch * (HSY * HSX) + (py + 1) * HSX + 1;
                float v0 = fmaf(d2[t][ng][bq],     u0, xc[qid]);
                float v1 = fmaf(d2[t][ng][bq + 2], u1, xc[qid + 8]);
                ob[(size_t)ch * HW + gx0] = v0;
                ob[(size_t)ch * HW + gx1] = v1;
                if (ch == 3) {
                    g_ch3[(size_t)b * HW + gy * NW + gx0] = v0;
                    g_ch3[(size_t)b * HW + gy * NW + gx1] = v1;
                }
            }
        }
    }
}

// mask: 4 pixels/thread, shared column maxes
__global__ void nca_mask(const float* __restrict__ x, float* __restrict__ out) {
    int idx = blockIdx.x * blockDim.x + threadIdx.x;
    if (idx >= NB * HW / 4) return;
    int b = idx / (HW / 4);
    int r = idx - b * (HW / 4);
    int i  = r / (NW / 4);
    int j0 = (r - i * (NW / 4)) * 4;

    const float* x3 = x + ((size_t)b * NC + 3) * HW;
    const float* n3 = g_ch3 + (size_t)b * HW;

    float cm0[6], cm1[6];
    #pragma unroll
    for (int k = 0; k < 6; ++k) {
        int jj = j0 - 1 + k;
        float a = -1e30f, c = -1e30f;
        if (jj >= 0 && jj < NW) {
            #pragma unroll
            for (int dy = -1; dy <= 1; ++dy) {
                int yy = i + dy;
                if (yy < 0 || yy >= NH) continue;
                a = fmaxf(a, x3[yy * NW + jj]);
                c = fmaxf(c, n3[yy * NW + jj]);
            }
        }
        cm0[k] = a; cm1[k] = c;
    }
    #pragma unroll
    for (int q = 0; q < 4; ++q) {
        float m0 = fmaxf(fmaxf(cm0[q], cm0[q + 1]), cm0[q + 2]);
        float m1 = fmaxf(fmaxf(cm1[q], cm1[q + 1]), cm1[q + 2]);
        if (!((m0 > 0.1f) && (m1 > 0.1f))) {
            float* ob = out + (size_t)b * NC * HW + i * NW + j0 + q;
            #pragma unroll
            for (int c = 0; c < NC; ++c) ob[(size_t)c * HW] = 0.f;
        }
    }
}

extern "C" void kernel_launch(void* const* d_in, const int* in_sizes, int n_in,
                              void* d_out, int out_size) {
    const float* x  = (const float*)d_in[0];
    const float* ur = (const float*)d_in[1];
    const float* w1 = (const float*)d_in[2];
    const float* b1 = (const float*)d_in[3];
    const float* w2 = (const float*)d_in[4];
    float* out = (float*)d_out;

    cudaFuncSetAttribute(nca_main, cudaFuncAttributeMaxDynamicSharedMemorySize, SM_BYTES);

    nca_prep<<<17, 256>>>(w1, b1, w2);

    dim3 grid(NW / TLX, NH / TLY, NB);
    nca_main<<<grid, 256, SM_BYTES>>>(x, ur, out);

    nca_mask<<<(NB * HW / 4 + 255) / 256, 256>>>(x, out);
}